// round 6
// baseline (speedup 1.0000x reference)
#include <cuda_runtime.h>
#include <math.h>

#define BB 4
#define CC 64
#define HH 128
#define WW 128
#define DD 256
#define NN 100
#define MAXDET 10
#define HWP (HH*WW)
#define SEG_OFF   0
#define MASK_OFF  (HWP*BB)
#define KEPT_OFF  (MASK_OFF + HWP*BB)
#define VALID_OFF (KEPT_OFF + BB*MAXDET*5)

#define TP 16                    // pixels per tile
#define XPAD 68                  // sx row stride (floats)
#define APAD 260                 // activation row stride (floats)
#define NPART 16                 // seg0 partial blocks
#define MLPGRID 296

// ---------------- device scratch ----------------
__device__ int   g_ibox[BB][MAXDET][4];
__device__ int   g_valid[BB][MAXDET];
__device__ float g_seg0;
__device__ float g_part[NPART][DD];
__device__ int   g_count;
__device__ int   g_list[BB*HWP];

typedef unsigned long long ull;

// ---------------- packed f32x2 helpers (sm_103a) ----------------
__device__ __forceinline__ ull fma2(ull a, ull b, ull c) {
    ull d;
    asm("fma.rn.f32x2 %0, %1, %2, %3;" : "=l"(d) : "l"(a), "l"(b), "l"(c));
    return d;
}
__device__ __forceinline__ ull pack2(float x) {
    unsigned u = __float_as_uint(x);
    ull r;
    asm("mov.b64 %0, {%1, %2};" : "=l"(r) : "r"(u), "r"(u));
    return r;
}
__device__ __forceinline__ void unpack2(ull v, float& lo, float& hi) {
    unsigned a, b;
    asm("mov.b64 {%0, %1}, %2;" : "=r"(a), "=r"(b) : "l"(v));
    lo = __uint_as_float(a);
    hi = __uint_as_float(b);
}

// ---------------- Kernel 1: NMS (blocks 0-3) + seg0 partials ------------
__global__ void __launch_bounds__(256) front_kernel(
        const float* __restrict__ rb,
        const float* __restrict__ b1v, const float* __restrict__ W2,
        float* __restrict__ out) {
    const int t = threadIdx.x;

    if (blockIdx.x >= BB) {
        const int blk = blockIdx.x - BB;
        const int d0 = blk * 16;
        float h1[16];
        #pragma unroll
        for (int j = 0; j < 16; j++) h1[j] = fmaxf(__ldg(&b1v[d0 + j]), 0.f);
        float acc = 0.f;
        #pragma unroll
        for (int j = 0; j < 16; j++) acc += h1[j] * __ldg(&W2[(d0 + j)*DD + t]);
        g_part[blk][t] = acc;
        return;
    }

    const int b = blockIdx.x;
    __shared__ float bx[NN*5];
    __shared__ float area[NN];
    __shared__ float iou[NN*NN];
    __shared__ int   s_any;
    __shared__ int   idxs[MAXDET];
    __shared__ int   hasA[MAXDET];

    for (int i = t; i < NN*5; i += 256) bx[i] = rb[b*NN*5 + i];
    if (t == 0) s_any = 0;
    __syncthreads();

    if (t < NN) {
        float a = fmaxf(bx[t*5+2]-bx[t*5+0], 0.f) * fmaxf(bx[t*5+3]-bx[t*5+1], 0.f);
        area[t] = a;
        if (bx[t*5+4] > 0.2f) atomicOr(&s_any, 1);
    }
    __syncthreads();

    for (int k = t; k < NN*NN; k += 256) {
        int i = k / NN, j = k - i*NN;
        float lx = fmaxf(bx[i*5+0], bx[j*5+0]);
        float ly = fmaxf(bx[i*5+1], bx[j*5+1]);
        float rx = fminf(bx[i*5+2], bx[j*5+2]);
        float ry = fminf(bx[i*5+3], bx[j*5+3]);
        float iw = fmaxf(rx - lx, 0.f);
        float ih = fmaxf(ry - ly, 0.f);
        float inter = iw * ih;
        iou[k] = inter / (area[i] + area[j] - inter + 1e-9f);
    }
    __syncthreads();

    if (t < 32) {
        const int l = t;
        const int anyv = s_any;
        float cf[4];
        int   act[4];
        #pragma unroll
        for (int m = 0; m < 4; m++) {
            int c = l + 32*m;
            bool ok = c < NN;
            cf[m]  = ok ? bx[c*5+4] : -INFINITY;
            act[m] = ok ? (anyv ? (cf[m] > 0.2f ? 1 : 0) : 1) : 0;
        }
        for (int it = 0; it < MAXDET; it++) {
            float bv = -INFINITY;
            int   bi = l;
            #pragma unroll
            for (int m = 0; m < 4; m++) {
                int c = l + 32*m;
                if (act[m] && cf[m] > bv) { bv = cf[m]; bi = c; }
            }
            #pragma unroll
            for (int off = 16; off; off >>= 1) {
                float v2 = __shfl_xor_sync(0xffffffffu, bv, off);
                int   i2 = __shfl_xor_sync(0xffffffffu, bi, off);
                if (v2 > bv || (v2 == bv && i2 < bi)) { bv = v2; bi = i2; }
            }
            bool has = bv > -INFINITY;
            if (l == 0) { idxs[it] = bi; hasA[it] = has ? 1 : 0; }
            if (has) {
                #pragma unroll
                for (int m = 0; m < 4; m++) {
                    int c = l + 32*m;
                    if (act[m] && (c == bi || iou[bi*NN + c] > 0.4f)) act[m] = 0;
                }
            }
        }
    }
    __syncthreads();

    if (t < MAXDET*5) {
        int det = t / 5, k = t - det*5;
        out[KEPT_OFF + b*MAXDET*5 + t] = bx[idxs[det]*5 + k];
    }
    if (t < MAXDET) {
        int kr = idxs[t];
        float x1f = bx[kr*5+0], y1f = bx[kr*5+1];
        float x2f = bx[kr*5+2], y2f = bx[kr*5+3];
        int v = hasA[t] && (x2f - x1f >= 1.f) && (y2f - y1f >= 1.f)
                        && (s_any ? 1 : (t < 5));
        out[VALID_OFF + b*MAXDET + t] = v ? 1.f : 0.f;
        g_valid[b][t] = v;
        int x1 = (int)floorf(x1f + 0.5f); x1 = min(max(x1, 0), WW);
        int y1 = (int)floorf(y1f + 0.5f); y1 = min(max(y1, 0), HH);
        int x2 = (int)floorf(x2f + 0.5f); x2 = min(max(x2, 0), WW);
        int y2 = (int)floorf(y2f + 0.5f); y2 = min(max(y2, 0), HH);
        g_ibox[b][t][0] = x1; g_ibox[b][t][1] = y1;
        g_ibox[b][t][2] = x2; g_ibox[b][t][3] = y2;
    }
}

// ---------------- Kernel 2: combine seg0 partials ----------------
__global__ void __launch_bounds__(256) combine_kernel(
        const float* __restrict__ b2v, const float* __restrict__ W3,
        const float* __restrict__ b3v) {
    __shared__ float red[256];
    const int t = threadIdx.x;
    float acc = b2v[t];
    #pragma unroll
    for (int blk = 0; blk < NPART; blk++) acc += g_part[blk][t];
    red[t] = fmaxf(acc, 0.f) * W3[t];
    __syncthreads();
    for (int off = 128; off; off >>= 1) {
        if (t < off) red[t] += red[t + off];
        __syncthreads();
    }
    if (t == 0) { g_seg0 = red[0] + b3v[0]; g_count = 0; }
}

// ---------------- Kernel 3: mask + default seg + compact ----------------
__global__ void mask_kernel(float* __restrict__ out) {
    int p = blockIdx.x * blockDim.x + threadIdx.x;
    if (p >= HWP) return;
    int h = p >> 7;
    int w = p & (WW - 1);
    float s0 = g_seg0;
    *(float4*)&out[SEG_OFF + p*BB] = make_float4(s0, s0, s0, s0);
    #pragma unroll
    for (int b = 0; b < BB; b++) {
        bool inside = false;
        #pragma unroll
        for (int k = 0; k < MAXDET; k++) {
            if (g_valid[b][k]) {
                inside |= (w >= g_ibox[b][k][0] && w < g_ibox[b][k][2] &&
                           h >= g_ibox[b][k][1] && h < g_ibox[b][k][3]);
            }
        }
        out[MASK_OFF + b*HWP + p] = inside ? 0.f : 1.f;
        if (inside) {
            int pos = atomicAdd(&g_count, 1);
            g_list[pos] = (b << 14) | p;
        }
    }
}

// ---------------- MLP pieces: thread = 8 feats x 8 px, 4-way k-split ------
// acc[fp][j]: fp = feature pair (f0+2fp, f0+2fp+1), j = pixel (pxb+j).
__device__ __forceinline__ void accum_quarter(
        const float* __restrict__ Wm, const float* __restrict__ act, int stride,
        ull acc[4][8], int f0, int k0, int klen) {
    const float* a0 = act;
    #pragma unroll 4
    for (int k = k0; k < k0 + klen; k++) {
        ulonglong2 w01 = *(const ulonglong2*)&Wm[k*DD + f0];
        ulonglong2 w23 = *(const ulonglong2*)&Wm[k*DD + f0 + 4];
        #pragma unroll
        for (int j = 0; j < 8; j++) {
            ull xs = pack2(a0[j*stride + k]);
            acc[0][j] = fma2(w01.x, xs, acc[0][j]);
            acc[1][j] = fma2(w01.y, xs, acc[1][j]);
            acc[2][j] = fma2(w23.x, xs, acc[2][j]);
            acc[3][j] = fma2(w23.y, xs, acc[3][j]);
        }
    }
}

template<bool RELU, bool FINAL>
__device__ __forceinline__ void combine_layer(
        float (*dest)[APAD], float (*s1)[APAD], float (*s2)[APAD],
        ull acc[4][8], const float* __restrict__ bias,
        const float* __restrict__ W3,
        int kq, int f0, int pxb, float* sp) {
    if (kq != 0) {
        float (*buf)[APAD] = (kq == 1) ? dest : (kq == 2) ? s1 : s2;
        #pragma unroll
        for (int j = 0; j < 8; j++) {
            float v0,v1,v2,v3,v4,v5,v6,v7;
            unpack2(acc[0][j], v0, v1);
            unpack2(acc[1][j], v2, v3);
            unpack2(acc[2][j], v4, v5);
            unpack2(acc[3][j], v6, v7);
            *(float4*)&buf[pxb+j][f0]   = make_float4(v0, v1, v2, v3);
            *(float4*)&buf[pxb+j][f0+4] = make_float4(v4, v5, v6, v7);
        }
    }
    __syncthreads();
    if (kq == 0) {
        float4 bA = *(const float4*)&bias[f0];
        float4 bB = *(const float4*)&bias[f0+4];
        float w30 = 0, w31 = 0, w32 = 0, w33 = 0, w34 = 0, w35 = 0, w36 = 0, w37 = 0;
        if (FINAL) {
            float4 wA = *(const float4*)&W3[f0];
            float4 wB = *(const float4*)&W3[f0+4];
            w30 = wA.x; w31 = wA.y; w32 = wA.z; w33 = wA.w;
            w34 = wB.x; w35 = wB.y; w36 = wB.z; w37 = wB.w;
        }
        #pragma unroll
        for (int j = 0; j < 8; j++) {
            float v[8];
            unpack2(acc[0][j], v[0], v[1]);
            unpack2(acc[1][j], v[2], v[3]);
            unpack2(acc[2][j], v[4], v[5]);
            unpack2(acc[3][j], v[6], v[7]);
            float4 d0 = *(const float4*)&dest[pxb+j][f0];
            float4 d1 = *(const float4*)&dest[pxb+j][f0+4];
            float4 e0 = *(const float4*)&s1[pxb+j][f0];
            float4 e1 = *(const float4*)&s1[pxb+j][f0+4];
            float4 g0 = *(const float4*)&s2[pxb+j][f0];
            float4 g1 = *(const float4*)&s2[pxb+j][f0+4];
            v[0] += bA.x + d0.x + e0.x + g0.x;
            v[1] += bA.y + d0.y + e0.y + g0.y;
            v[2] += bA.z + d0.z + e0.z + g0.z;
            v[3] += bA.w + d0.w + e0.w + g0.w;
            v[4] += bB.x + d1.x + e1.x + g1.x;
            v[5] += bB.y + d1.y + e1.y + g1.y;
            v[6] += bB.z + d1.z + e1.z + g1.z;
            v[7] += bB.w + d1.w + e1.w + g1.w;
            if (RELU) {
                #pragma unroll
                for (int i = 0; i < 8; i++) v[i] = fmaxf(v[i], 0.f);
            }
            if (FINAL) {
                sp[j] = v[0]*w30 + v[1]*w31 + v[2]*w32 + v[3]*w33
                      + v[4]*w34 + v[5]*w35 + v[6]*w36 + v[7]*w37;
            } else {
                *(float4*)&dest[pxb+j][f0]   = make_float4(v[0], v[1], v[2], v[3]);
                *(float4*)&dest[pxb+j][f0+4] = make_float4(v[4], v[5], v[6], v[7]);
            }
        }
    }
    __syncthreads();
}

// ---------------- Kernel 4: persistent compacted-tile MLP ----------------
__global__ void __launch_bounds__(256) mlp_kernel(
        const float* __restrict__ x,
        const float* __restrict__ W_sem, const float* __restrict__ b_sem,
        const float* __restrict__ W1, const float* __restrict__ b1,
        const float* __restrict__ W2, const float* __restrict__ b2,
        const float* __restrict__ W3, const float* __restrict__ b3,
        float* __restrict__ out) {
    __shared__ __align__(16) float sx[TP][XPAD];
    __shared__ __align__(16) float sA[TP][APAD];
    __shared__ __align__(16) float sB[TP][APAD];
    __shared__ __align__(16) float sS1[TP][APAD];
    __shared__ __align__(16) float sS2[TP][APAD];
    __shared__ int spix[TP];

    const int count  = g_count;
    const int ntiles = (count + TP - 1) / TP;
    const int tid  = threadIdx.x;
    const int warp = tid >> 5;
    const int l    = tid & 31;
    const int kq   = warp >> 1;        // 0..3 k-quarter
    const int ph   = warp & 1;         // pixel half
    const int f0   = l * 8;            // 8 consecutive features per lane
    const int pxb  = ph * 8;

    for (int tile = blockIdx.x; tile < ntiles; tile += gridDim.x) {
        const int base = tile * TP;
        const int rem  = min(count - base, TP);
        if (tid < TP) spix[tid] = g_list[tid < rem ? base + tid : base];
        __syncthreads();

        for (int i = tid; i < CC*TP; i += 256) {
            int c = i >> 4, p = i & (TP - 1);
            int gid = spix[p];
            sx[p][c] = x[(((gid >> 14) << 6) + c) * HWP + (gid & (HWP - 1))];
        }
        __syncthreads();

        ull acc[4][8];
        float sp[8];

        // Layer 0: 64 -> 256 (no relu), dest sA
        #pragma unroll
        for (int fp = 0; fp < 4; fp++)
            #pragma unroll
            for (int j = 0; j < 8; j++) acc[fp][j] = 0;
        accum_quarter(W_sem, &sx[pxb][0], XPAD, acc, f0, kq*16, 16);
        combine_layer<false,false>(sA, sS1, sS2, acc, b_sem, nullptr, kq, f0, pxb, sp);

        // Layer 1: 256 -> 256 relu, dest sB
        #pragma unroll
        for (int fp = 0; fp < 4; fp++)
            #pragma unroll
            for (int j = 0; j < 8; j++) acc[fp][j] = 0;
        accum_quarter(W1, &sA[pxb][0], APAD, acc, f0, kq*64, 64);
        combine_layer<true,false>(sB, sS1, sS2, acc, b1, nullptr, kq, f0, pxb, sp);

        // Layer 2: 256 -> 256 relu + fused W3 dot (kq1 stages into sA)
        #pragma unroll
        for (int fp = 0; fp < 4; fp++)
            #pragma unroll
            for (int j = 0; j < 8; j++) acc[fp][j] = 0;
        accum_quarter(W2, &sB[pxb][0], APAD, acc, f0, kq*64, 64);
        combine_layer<true,true>(sA, sS1, sS2, acc, b2, W3, kq, f0, pxb, sp);

        if (kq == 0) {
            #pragma unroll
            for (int off = 16; off; off >>= 1) {
                #pragma unroll
                for (int j = 0; j < 8; j++)
                    sp[j] += __shfl_xor_sync(0xffffffffu, sp[j], off);
            }
            if (l == 0) {
                float bb = b3[0];
                #pragma unroll
                for (int j = 0; j < 8; j++) {
                    int gid = spix[pxb + j];
                    out[SEG_OFF + (gid & (HWP-1))*BB + (gid >> 14)] = sp[j] + bb;
                }
            }
        }
        __syncthreads();
    }
}

// ---------------- launch ----------------
extern "C" void kernel_launch(void* const* d_in, const int* in_sizes, int n_in,
                              void* d_out, int out_size) {
    (void)in_sizes; (void)n_in; (void)out_size;
    const float* x     = (const float*)d_in[0];
    const float* rb    = (const float*)d_in[1];
    const float* W_sem = (const float*)d_in[2];
    const float* b_sem = (const float*)d_in[3];
    const float* W1    = (const float*)d_in[4];
    const float* b1    = (const float*)d_in[5];
    const float* W2    = (const float*)d_in[6];
    const float* b2    = (const float*)d_in[7];
    const float* W3    = (const float*)d_in[8];
    const float* b3    = (const float*)d_in[9];
    float* out = (float*)d_out;

    front_kernel<<<BB + NPART, 256>>>(rb, b1, W2, out);
    combine_kernel<<<1, 256>>>(b2, W3, b3);
    mask_kernel<<<HWP/256, 256>>>(out);
    mlp_kernel<<<MLPGRID, 256>>>(x, W_sem, b_sem, W1, b1, W2, b2, W3, b3, out);
}

// round 7
// speedup vs baseline: 1.2217x; 1.2217x over previous
#include <cuda_runtime.h>
#include <math.h>

#define BB 4
#define CC 64
#define HH 128
#define WW 128
#define DD 256
#define NN 100
#define MAXDET 10
#define HWP (HH*WW)
#define SEG_OFF   0
#define MASK_OFF  (HWP*BB)
#define KEPT_OFF  (MASK_OFF + HWP*BB)
#define VALID_OFF (KEPT_OFF + BB*MAXDET*5)

#define TP 16                    // pixels per tile
#define RS 20                    // act row stride in floats (80B, 16B aligned)
#define NPART 16                 // seg0 partial blocks
#define MAXTILES 723             // ceil(4*10*17*17/16)

// ---------------- device scratch ----------------
__device__ int   g_ibox[BB][MAXDET][4];
__device__ int   g_valid[BB][MAXDET];
__device__ float g_seg0;
__device__ float g_part[NPART][DD];
__device__ int   g_count;
__device__ int   g_list[BB*HWP];

typedef unsigned long long ull;

__device__ __forceinline__ ull fma2(ull a, ull b, ull c) {
    ull d;
    asm("fma.rn.f32x2 %0, %1, %2, %3;" : "=l"(d) : "l"(a), "l"(b), "l"(c));
    return d;
}
__device__ __forceinline__ ull pack2(float x) {
    unsigned u = __float_as_uint(x);
    ull r;
    asm("mov.b64 %0, {%1, %2};" : "=l"(r) : "r"(u), "r"(u));
    return r;
}
__device__ __forceinline__ void unpack2(ull v, float& lo, float& hi) {
    unsigned a, b;
    asm("mov.b64 {%0, %1}, %2;" : "=r"(a), "=r"(b) : "l"(v));
    lo = __uint_as_float(a);
    hi = __uint_as_float(b);
}

// ---------------- Kernel 1: NMS (blocks 0-3) + seg0 partials ------------
__global__ void __launch_bounds__(256) front_kernel(
        const float* __restrict__ rb,
        const float* __restrict__ b1v, const float* __restrict__ W2,
        float* __restrict__ out) {
    const int t = threadIdx.x;

    if (blockIdx.x >= BB) {
        const int blk = blockIdx.x - BB;
        const int d0 = blk * 16;
        float h1[16];
        #pragma unroll
        for (int j = 0; j < 16; j++) h1[j] = fmaxf(__ldg(&b1v[d0 + j]), 0.f);
        float acc = 0.f;
        #pragma unroll
        for (int j = 0; j < 16; j++) acc += h1[j] * __ldg(&W2[(d0 + j)*DD + t]);
        g_part[blk][t] = acc;
        return;
    }

    const int b = blockIdx.x;
    __shared__ float bx[NN*5];
    __shared__ float area[NN];
    __shared__ float iou[NN*NN];
    __shared__ int   s_any;
    __shared__ int   idxs[MAXDET];
    __shared__ int   hasA[MAXDET];

    for (int i = t; i < NN*5; i += 256) bx[i] = rb[b*NN*5 + i];
    if (t == 0) s_any = 0;
    __syncthreads();

    if (t < NN) {
        float a = fmaxf(bx[t*5+2]-bx[t*5+0], 0.f) * fmaxf(bx[t*5+3]-bx[t*5+1], 0.f);
        area[t] = a;
        if (bx[t*5+4] > 0.2f) atomicOr(&s_any, 1);
    }
    __syncthreads();

    for (int k = t; k < NN*NN; k += 256) {
        int i = k / NN, j = k - i*NN;
        float lx = fmaxf(bx[i*5+0], bx[j*5+0]);
        float ly = fmaxf(bx[i*5+1], bx[j*5+1]);
        float rx = fminf(bx[i*5+2], bx[j*5+2]);
        float ry = fminf(bx[i*5+3], bx[j*5+3]);
        float iw = fmaxf(rx - lx, 0.f);
        float ih = fmaxf(ry - ly, 0.f);
        float inter = iw * ih;
        iou[k] = inter / (area[i] + area[j] - inter + 1e-9f);
    }
    __syncthreads();

    if (t < 32) {
        const int l = t;
        const int anyv = s_any;
        float cf[4];
        int   act[4];
        #pragma unroll
        for (int m = 0; m < 4; m++) {
            int c = l + 32*m;
            bool ok = c < NN;
            cf[m]  = ok ? bx[c*5+4] : -INFINITY;
            act[m] = ok ? (anyv ? (cf[m] > 0.2f ? 1 : 0) : 1) : 0;
        }
        for (int it = 0; it < MAXDET; it++) {
            float bv = -INFINITY;
            int   bi = l;
            #pragma unroll
            for (int m = 0; m < 4; m++) {
                int c = l + 32*m;
                if (act[m] && cf[m] > bv) { bv = cf[m]; bi = c; }
            }
            #pragma unroll
            for (int off = 16; off; off >>= 1) {
                float v2 = __shfl_xor_sync(0xffffffffu, bv, off);
                int   i2 = __shfl_xor_sync(0xffffffffu, bi, off);
                if (v2 > bv || (v2 == bv && i2 < bi)) { bv = v2; bi = i2; }
            }
            bool has = bv > -INFINITY;
            if (l == 0) { idxs[it] = bi; hasA[it] = has ? 1 : 0; }
            if (has) {
                #pragma unroll
                for (int m = 0; m < 4; m++) {
                    int c = l + 32*m;
                    if (act[m] && (c == bi || iou[bi*NN + c] > 0.4f)) act[m] = 0;
                }
            }
        }
    }
    __syncthreads();

    if (t < MAXDET*5) {
        int det = t / 5, k = t - det*5;
        out[KEPT_OFF + b*MAXDET*5 + t] = bx[idxs[det]*5 + k];
    }
    if (t < MAXDET) {
        int kr = idxs[t];
        float x1f = bx[kr*5+0], y1f = bx[kr*5+1];
        float x2f = bx[kr*5+2], y2f = bx[kr*5+3];
        int v = hasA[t] && (x2f - x1f >= 1.f) && (y2f - y1f >= 1.f)
                        && (s_any ? 1 : (t < 5));
        out[VALID_OFF + b*MAXDET + t] = v ? 1.f : 0.f;
        g_valid[b][t] = v;
        int x1 = (int)floorf(x1f + 0.5f); x1 = min(max(x1, 0), WW);
        int y1 = (int)floorf(y1f + 0.5f); y1 = min(max(y1, 0), HH);
        int x2 = (int)floorf(x2f + 0.5f); x2 = min(max(x2, 0), WW);
        int y2 = (int)floorf(y2f + 0.5f); y2 = min(max(y2, 0), HH);
        g_ibox[b][t][0] = x1; g_ibox[b][t][1] = y1;
        g_ibox[b][t][2] = x2; g_ibox[b][t][3] = y2;
    }
}

// ---------------- Kernel 2: combine seg0 partials ----------------
__global__ void __launch_bounds__(256) combine_kernel(
        const float* __restrict__ b2v, const float* __restrict__ W3,
        const float* __restrict__ b3v) {
    __shared__ float red[256];
    const int t = threadIdx.x;
    float acc = b2v[t];
    #pragma unroll
    for (int blk = 0; blk < NPART; blk++) acc += g_part[blk][t];
    red[t] = fmaxf(acc, 0.f) * W3[t];
    __syncthreads();
    for (int off = 128; off; off >>= 1) {
        if (t < off) red[t] += red[t + off];
        __syncthreads();
    }
    if (t == 0) { g_seg0 = red[0] + b3v[0]; g_count = 0; }
}

// ---------------- Kernel 3: mask + default seg + compact ----------------
__global__ void mask_kernel(float* __restrict__ out) {
    int p = blockIdx.x * blockDim.x + threadIdx.x;
    if (p >= HWP) return;
    int h = p >> 7;
    int w = p & (WW - 1);
    float s0 = g_seg0;
    *(float4*)&out[SEG_OFF + p*BB] = make_float4(s0, s0, s0, s0);
    #pragma unroll
    for (int b = 0; b < BB; b++) {
        bool inside = false;
        #pragma unroll
        for (int k = 0; k < MAXDET; k++) {
            if (g_valid[b][k]) {
                inside |= (w >= g_ibox[b][k][0] && w < g_ibox[b][k][2] &&
                           h >= g_ibox[b][k][1] && h < g_ibox[b][k][3]);
            }
        }
        out[MASK_OFF + b*HWP + p] = inside ? 0.f : 1.f;
        if (inside) {
            int pos = atomicAdd(&g_count, 1);
            g_list[pos] = (b << 14) | p;
        }
    }
}

// ---------------- MLP accumulate: 2 feats x 8 px per thread --------------
// act points at act[k0-th row][pb]; row stride RS floats; warp-uniform reads.
__device__ __forceinline__ void accum8(
        const float* __restrict__ Wm, const float* __restrict__ act,
        ull acc[2][4], int f0, int k0, int klen) {
    const float* a = act + (size_t)k0 * RS;
    const float* w = Wm + (size_t)k0 * DD + f0;
    #pragma unroll 8
    for (int k = 0; k < klen; k++) {
        float2 wf = *(const float2*)w;
        ull w0 = pack2(wf.x), w1 = pack2(wf.y);
        ulonglong2 x01 = *(const ulonglong2*)(a);
        ulonglong2 x23 = *(const ulonglong2*)(a + 4);
        acc[0][0] = fma2(w0, x01.x, acc[0][0]);
        acc[0][1] = fma2(w0, x01.y, acc[0][1]);
        acc[0][2] = fma2(w0, x23.x, acc[0][2]);
        acc[0][3] = fma2(w0, x23.y, acc[0][3]);
        acc[1][0] = fma2(w1, x01.x, acc[1][0]);
        acc[1][1] = fma2(w1, x01.y, acc[1][1]);
        acc[1][2] = fma2(w1, x23.x, acc[1][2]);
        acc[1][3] = fma2(w1, x23.y, acc[1][3]);
        a += RS;
        w += DD;
    }
}

// ---------------- Kernel 4: compacted-tile MLP, 512 thr, 2-way k-split ----
__global__ void __launch_bounds__(512) mlp_kernel(
        const float* __restrict__ x,
        const float* __restrict__ W_sem, const float* __restrict__ b_sem,
        const float* __restrict__ W1, const float* __restrict__ b1,
        const float* __restrict__ W2, const float* __restrict__ b2,
        const float* __restrict__ W3, const float* __restrict__ b3,
        float* __restrict__ out) {
    __shared__ __align__(16) float sx[CC][RS];
    __shared__ __align__(16) float sA[DD][RS];
    __shared__ __align__(16) float sB[DD][RS];
    __shared__ __align__(16) float sP[DD][RS];   // kp=1 partials
    __shared__ float stage[128][17];
    __shared__ int spix[TP];

    const int count  = g_count;
    const int ntiles = (count + TP - 1) / TP;
    const int tile = blockIdx.x;
    if (tile >= ntiles) return;
    const int base = tile * TP;
    const int rem  = min(count - base, TP);

    const int tid = threadIdx.x;     // 512
    const int kp  = tid >> 8;        // k half
    const int ph  = (tid >> 7) & 1;  // pixel half
    const int ft  = tid & 127;       // feature-pair index
    const int f0  = ft * 2;
    const int pb  = ph * 8;

    if (tid < TP) spix[tid] = g_list[tid < rem ? base + tid : base];
    __syncthreads();

    for (int i = tid; i < CC*TP; i += 512) {
        int c = i >> 4, p = i & (TP - 1);
        int gid = spix[p];
        sx[c][p] = x[(((gid >> 14) << 6) + c) * HWP + (gid & (HWP - 1))];
    }
    __syncthreads();

    ull acc[2][4];
    float sp[8];

    const float* acts[3] = { &sx[0][pb], &sA[0][pb], &sB[0][pb] };
    float (*dests[3])[RS] = { sA, sB, nullptr };
    const float* Ws[3]   = { W_sem, W1, W2 };
    const float* bs[3]   = { b_sem, b1, b2 };
    const int    Ks[3]   = { CC, DD, DD };

    #pragma unroll
    for (int layer = 0; layer < 3; layer++) {
        #pragma unroll
        for (int j = 0; j < 4; j++) { acc[0][j] = 0; acc[1][j] = 0; }
        const int kh = Ks[layer] >> 1;
        accum8(Ws[layer], acts[layer], acc, f0, kp * kh, kh);

        if (kp == 1) {
            float v[8];
            unpack2(acc[0][0], v[0], v[1]);
            unpack2(acc[0][1], v[2], v[3]);
            unpack2(acc[0][2], v[4], v[5]);
            unpack2(acc[0][3], v[6], v[7]);
            *(float4*)&sP[f0][pb]     = make_float4(v[0], v[1], v[2], v[3]);
            *(float4*)&sP[f0][pb+4]   = make_float4(v[4], v[5], v[6], v[7]);
            unpack2(acc[1][0], v[0], v[1]);
            unpack2(acc[1][1], v[2], v[3]);
            unpack2(acc[1][2], v[4], v[5]);
            unpack2(acc[1][3], v[6], v[7]);
            *(float4*)&sP[f0+1][pb]   = make_float4(v[0], v[1], v[2], v[3]);
            *(float4*)&sP[f0+1][pb+4] = make_float4(v[4], v[5], v[6], v[7]);
        }
        __syncthreads();
        if (kp == 0) {
            float2 bb = *(const float2*)&bs[layer][f0];
            float v0[8], v1[8];
            unpack2(acc[0][0], v0[0], v0[1]);
            unpack2(acc[0][1], v0[2], v0[3]);
            unpack2(acc[0][2], v0[4], v0[5]);
            unpack2(acc[0][3], v0[6], v0[7]);
            unpack2(acc[1][0], v1[0], v1[1]);
            unpack2(acc[1][1], v1[2], v1[3]);
            unpack2(acc[1][2], v1[4], v1[5]);
            unpack2(acc[1][3], v1[6], v1[7]);
            float4 p00 = *(const float4*)&sP[f0][pb];
            float4 p01 = *(const float4*)&sP[f0][pb+4];
            float4 p10 = *(const float4*)&sP[f0+1][pb];
            float4 p11 = *(const float4*)&sP[f0+1][pb+4];
            v0[0] += bb.x + p00.x; v0[1] += bb.x + p00.y;
            v0[2] += bb.x + p00.z; v0[3] += bb.x + p00.w;
            v0[4] += bb.x + p01.x; v0[5] += bb.x + p01.y;
            v0[6] += bb.x + p01.z; v0[7] += bb.x + p01.w;
            v1[0] += bb.y + p10.x; v1[1] += bb.y + p10.y;
            v1[2] += bb.y + p10.z; v1[3] += bb.y + p10.w;
            v1[4] += bb.y + p11.x; v1[5] += bb.y + p11.y;
            v1[6] += bb.y + p11.z; v1[7] += bb.y + p11.w;
            if (layer > 0) {
                #pragma unroll
                for (int i = 0; i < 8; i++) {
                    v0[i] = fmaxf(v0[i], 0.f);
                    v1[i] = fmaxf(v1[i], 0.f);
                }
            }
            if (layer < 2) {
                float (*dst)[RS] = dests[layer];
                *(float4*)&dst[f0][pb]     = make_float4(v0[0], v0[1], v0[2], v0[3]);
                *(float4*)&dst[f0][pb+4]   = make_float4(v0[4], v0[5], v0[6], v0[7]);
                *(float4*)&dst[f0+1][pb]   = make_float4(v1[0], v1[1], v1[2], v1[3]);
                *(float4*)&dst[f0+1][pb+4] = make_float4(v1[4], v1[5], v1[6], v1[7]);
            } else {
                float2 w3 = *(const float2*)&W3[f0];
                #pragma unroll
                for (int i = 0; i < 8; i++)
                    sp[i] = v0[i]*w3.x + v1[i]*w3.y;
            }
        }
        __syncthreads();
    }

    // stage final partial dots and reduce: stage[ft][px]
    if (kp == 0) {
        #pragma unroll
        for (int i = 0; i < 8; i++) stage[ft][pb + i] = sp[i];
    }
    __syncthreads();

    // 16 warps: warp w reduces pixel w over 128 ft rows
    const int warp = tid >> 5;
    const int l    = tid & 31;
    if (warp < TP) {
        float s = stage[l][warp] + stage[l+32][warp]
                + stage[l+64][warp] + stage[l+96][warp];
        #pragma unroll
        for (int off = 16; off; off >>= 1)
            s += __shfl_xor_sync(0xffffffffu, s, off);
        if (l == 0 && warp < rem) {
            int gid = spix[warp];
            out[SEG_OFF + (gid & (HWP-1))*BB + (gid >> 14)] = s + b3[0];
        }
    }
}

// ---------------- launch ----------------
extern "C" void kernel_launch(void* const* d_in, const int* in_sizes, int n_in,
                              void* d_out, int out_size) {
    (void)in_sizes; (void)n_in; (void)out_size;
    const float* x     = (const float*)d_in[0];
    const float* rb    = (const float*)d_in[1];
    const float* W_sem = (const float*)d_in[2];
    const float* b_sem = (const float*)d_in[3];
    const float* W1    = (const float*)d_in[4];
    const float* b1    = (const float*)d_in[5];
    const float* W2    = (const float*)d_in[6];
    const float* b2    = (const float*)d_in[7];
    const float* W3    = (const float*)d_in[8];
    const float* b3    = (const float*)d_in[9];
    float* out = (float*)d_out;

    front_kernel<<<BB + NPART, 256>>>(rb, b1, W2, out);
    combine_kernel<<<1, 256>>>(b2, W3, b3);
    mask_kernel<<<HWP/256, 256>>>(out);
    mlp_kernel<<<MAXTILES, 512>>>(x, W_sem, b_sem, W1, b1, W2, b2, W3, b3, out);
}